// round 14
// baseline (speedup 1.0000x reference)
#include <cuda_runtime.h>
#include <math.h>
#include <stdint.h>

// Problem constants
#define BB 2
#define SS 2048
#define DD 768
#define HH 12
#define HDIM 64
#define NT (BB*SS)      // 4096 tokens
#define NBH (BB*HH)     // 24

typedef unsigned long long u64;

// ---------------------------------------------------------------------------
// f32x2 packed helpers
// ---------------------------------------------------------------------------
__device__ __forceinline__ u64 pk2(float lo, float hi) {
    u64 r; asm("mov.b64 %0, {%1, %2};" : "=l"(r) : "f"(lo), "f"(hi)); return r;
}
__device__ __forceinline__ float2 up2(u64 v) {
    float lo, hi; asm("mov.b64 {%0, %1}, %2;" : "=f"(lo), "=f"(hi) : "l"(v));
    return make_float2(lo, hi);
}
__device__ __forceinline__ void fma2(u64& d, u64 a, u64 b) {
    asm("fma.rn.f32x2 %0, %1, %2, %0;" : "+l"(d) : "l"(a), "l"(b));
}
__device__ __forceinline__ void add2(u64& d, u64 a) {
    asm("add.rn.f32x2 %0, %0, %1;" : "+l"(d) : "l"(a));
}
__device__ __forceinline__ float ex2(float x) {
    float r; asm("ex2.approx.f32 %0, %1;" : "=f"(r) : "f"(x)); return r;
}

// ---------------------------------------------------------------------------
// Device scratch
// ---------------------------------------------------------------------------
__device__ float g_q[(size_t)NT * DD];        // [b,s,d]
__device__ float g_k[(size_t)NT * DD];
__device__ float g_v[(size_t)NT * DD];
__device__ float g_att[(size_t)NT * DD];

#define TKK 16
#define NKT (DD / TKK)         // 48
#define TM 128

// ---------------------------------------------------------------------------
// GEMM (fused-3), templated on tile-N (FROZEN — proven optimal round 6/13).
// ---------------------------------------------------------------------------
template<int BN>
__global__ __launch_bounds__(256, 2)
void gemm3t(const float* __restrict__ A,
            const float* __restrict__ w0, const float* __restrict__ w1,
            const float* __restrict__ w2,
            const float* __restrict__ b0, const float* __restrict__ b1,
            const float* __restrict__ b2,
            float* __restrict__ o0, float* __restrict__ o1,
            float* __restrict__ o2)
{
    constexpr int NB   = DD / BN;
    constexpr int BPAD = BN + 4;
    constexpr int NJ   = BN / 32;
    constexpr int NLB  = BN / 64;
    constexpr int NCT  = BN / 16;

    __shared__ __align__(16) float sA[2][TKK][132];
    __shared__ __align__(16) float sB[2][TKK][BPAD];

    const int sel = blockIdx.y / NB;
    const float* W    = (sel == 0) ? w0 : (sel == 1) ? w1 : w2;
    const float* bias = (sel == 0) ? b0 : (sel == 1) ? b1 : b2;
    float* out        = (sel == 0) ? o0 : (sel == 1) ? o1 : o2;

    const int tid = threadIdx.x;
    const int tx = tid & 15;
    const int ty = tid >> 4;
    const int m0 = blockIdx.x * TM;
    const int n0 = (blockIdx.y % NB) * BN;

    const int i0 = tid * 2, i1 = tid * 2 + 1;
    const int ar  = i0 >> 2;
    const int ak0 = (i0 & 3) << 2;
    const int ak1 = (i1 & 3) << 2;
    int bk[NLB], bc[NLB];
    #pragma unroll
    for (int t = 0; t < NLB; t++) {
        const int idx = tid + t * 256;
        bk[t] = idx / (BN / 4);
        bc[t] = (idx % (BN / 4)) * 4;
    }

    u64 acc[8][NJ];
    #pragma unroll
    for (int i = 0; i < 8; i++)
        #pragma unroll
        for (int j = 0; j < NJ; j++) acc[i][j] = 0ull;

    float4 pa0 = *(const float4*)(A + (size_t)(m0 + ar) * DD + ak0);
    float4 pa1 = *(const float4*)(A + (size_t)(m0 + ar) * DD + ak1);
    float4 pb[NLB];
    #pragma unroll
    for (int t = 0; t < NLB; t++)
        pb[t] = *(const float4*)(W + (size_t)bk[t] * DD + n0 + bc[t]);

    sA[0][ak0 + 0][ar] = pa0.x; sA[0][ak0 + 1][ar] = pa0.y;
    sA[0][ak0 + 2][ar] = pa0.z; sA[0][ak0 + 3][ar] = pa0.w;
    sA[0][ak1 + 0][ar] = pa1.x; sA[0][ak1 + 1][ar] = pa1.y;
    sA[0][ak1 + 2][ar] = pa1.z; sA[0][ak1 + 3][ar] = pa1.w;
    #pragma unroll
    for (int t = 0; t < NLB; t++)
        *(float4*)&sB[0][bk[t]][bc[t]] = pb[t];

    for (int kt = 0; kt < NKT; kt++) {
        const int cur = kt & 1;
        if (kt + 1 < NKT) {
            const int k0 = (kt + 1) * TKK;
            pa0 = *(const float4*)(A + (size_t)(m0 + ar) * DD + k0 + ak0);
            pa1 = *(const float4*)(A + (size_t)(m0 + ar) * DD + k0 + ak1);
            #pragma unroll
            for (int t = 0; t < NLB; t++)
                pb[t] = *(const float4*)(W + (size_t)(k0 + bk[t]) * DD + n0 + bc[t]);
        }
        __syncthreads();

        #pragma unroll
        for (int kk = 0; kk < TKK; kk++) {
            float4 a0 = *(float4*)&sA[cur][kk][ty * 8];
            float4 a1 = *(float4*)&sA[cur][kk][ty * 8 + 4];
            u64 bp[NJ];
            #pragma unroll
            for (int g = 0; g < NJ / 2; g++) {
                ulonglong2 bq = *(ulonglong2*)&sB[cur][kk][tx * NCT + g * 4];
                bp[2 * g] = bq.x; bp[2 * g + 1] = bq.y;
            }
            float av[8] = { a0.x, a0.y, a0.z, a0.w, a1.x, a1.y, a1.z, a1.w };
            #pragma unroll
            for (int i = 0; i < 8; i++) {
                u64 as = pk2(av[i], av[i]);
                #pragma unroll
                for (int j = 0; j < NJ; j++) fma2(acc[i][j], as, bp[j]);
            }
        }

        if (kt + 1 < NKT) {
            const int nxt = cur ^ 1;
            sA[nxt][ak0 + 0][ar] = pa0.x; sA[nxt][ak0 + 1][ar] = pa0.y;
            sA[nxt][ak0 + 2][ar] = pa0.z; sA[nxt][ak0 + 3][ar] = pa0.w;
            sA[nxt][ak1 + 0][ar] = pa1.x; sA[nxt][ak1 + 1][ar] = pa1.y;
            sA[nxt][ak1 + 2][ar] = pa1.z; sA[nxt][ak1 + 3][ar] = pa1.w;
            #pragma unroll
            for (int t = 0; t < NLB; t++)
                *(float4*)&sB[nxt][bk[t]][bc[t]] = pb[t];
        }
    }

    #pragma unroll
    for (int i = 0; i < 8; i++) {
        float* dst = out + (size_t)(m0 + ty * 8 + i) * DD + n0 + tx * NCT;
        #pragma unroll
        for (int g = 0; g < NJ / 2; g++) {
            float4 bv = *(const float4*)(bias + n0 + tx * NCT + g * 4);
            float2 cl = up2(acc[i][2 * g]);
            float2 ch = up2(acc[i][2 * g + 1]);
            float4 o4 = make_float4(cl.x + bv.x, cl.y + bv.y,
                                    ch.x + bv.z, ch.y + bv.w);
            *(float4*)(dst + g * 4) = o4;
        }
    }
}

// ---------------------------------------------------------------------------
// FFMA2 flash attention, causal, fp32, no-max + ex2.
// AQ=64 x AK=64 tiles, 4q x 4k microtile -> 69.6KB smem -> 3 CTAs/SM
// (24 warps/SM) for latency hiding. Reg budget 84 (launch_bounds 256,3).
// ---------------------------------------------------------------------------
#define AQ 64
#define AP 68
#define ATTN_SMEM (4 * 64 * AP * 4)   // 69632 B
#define QSCL 0.18033688f   // 0.125 * log2(e)

__global__ __launch_bounds__(256, 3)
void attn_f2(const float* __restrict__ Q, const float* __restrict__ K,
             const float* __restrict__ V, float* __restrict__ Oo)
{
    extern __shared__ __align__(16) float sm[];
    float (*sQt)[AP] = (float(*)[AP])(sm);                 // [d][qrow]
    float (*sKt)[AP] = (float(*)[AP])(sm + 64 * AP);       // [d][kcol]
    float (*sV )[AP] = (float(*)[AP])(sm + 2 * 64 * AP);   // [k][d]
    float (*sPt)[AP] = (float(*)[AP])(sm + 3 * 64 * AP);   // [k][qrow]

    const int tid = threadIdx.x;
    const int tx = tid & 15;               // k-col / d group (4 each)
    const int ty = tid >> 4;               // q-row group (4 each)
    const int qt = (SS / AQ - 1) - blockIdx.x;   // 31..0, heavy first
    const int bh = blockIdx.y;
    const int b_ = bh / HH, h_ = bh % HH;

    const float* Qb = Q + (size_t)b_ * SS * DD + h_ * HDIM;
    const float* Kb = K + (size_t)b_ * SS * DD + h_ * HDIM;
    const float* Vb = V + (size_t)b_ * SS * DD + h_ * HDIM;

    // Load Q tile transposed, pre-scaled into ex2 units (4 float4 / thread)
    #pragma unroll
    for (int l = 0; l < 4; l++) {
        const int idx = tid + l * 256;
        const int r = idx >> 4, d0 = (idx & 15) << 2;
        float4 v4 = *(const float4*)(Qb + (size_t)(qt * AQ + r) * DD + d0);
        sQt[d0 + 0][r] = v4.x * QSCL; sQt[d0 + 1][r] = v4.y * QSCL;
        sQt[d0 + 2][r] = v4.z * QSCL; sQt[d0 + 3][r] = v4.w * QSCL;
    }

    u64 lsum2[2];                // packed row-sums (rows 2ip, 2ip+1)
    u64 o2[2][4];
    #pragma unroll
    for (int ip = 0; ip < 2; ip++) {
        lsum2[ip] = 0ull;
        #pragma unroll
        for (int j = 0; j < 4; j++) o2[ip][j] = 0ull;
    }

    const int njt = qt + 1;
    for (int jt = 0; jt < njt; jt++) {
        __syncthreads();   // protect sKt/sV/sPt from previous readers
        #pragma unroll
        for (int l = 0; l < 4; l++) {
            const int idx = tid + l * 256;
            const int r = idx >> 4, d0 = (idx & 15) << 2;
            float4 kv = *(const float4*)(Kb + (size_t)(jt * AQ + r) * DD + d0);
            sKt[d0 + 0][r] = kv.x; sKt[d0 + 1][r] = kv.y;
            sKt[d0 + 2][r] = kv.z; sKt[d0 + 3][r] = kv.w;
            *(float4*)&sV[r][d0] =
                *(const float4*)(Vb + (size_t)(jt * AQ + r) * DD + d0);
        }
        __syncthreads();

        // ---- QK scores (4q x 4k per thread; q packed in pairs) ----
        u64 sc2[2][4];
        #pragma unroll
        for (int ip = 0; ip < 2; ip++)
            #pragma unroll
            for (int j = 0; j < 4; j++) sc2[ip][j] = 0ull;

        #pragma unroll 8
        for (int dd = 0; dd < 64; dd++) {
            ulonglong2 qa = *(ulonglong2*)&sQt[dd][ty * 4];
            u64 ap[2] = { qa.x, qa.y };
            float4 kv = *(float4*)&sKt[dd][tx * 4];
            float kr[4] = { kv.x, kv.y, kv.z, kv.w };
            #pragma unroll
            for (int j = 0; j < 4; j++) {
                u64 ks = pk2(kr[j], kr[j]);
                #pragma unroll
                for (int ip = 0; ip < 2; ip++) fma2(sc2[ip][j], ap[ip], ks);
            }
        }

        // ---- p = ex2(score); mask only on the diagonal tile ----
        const bool msk = (jt == qt);
        #pragma unroll
        for (int ip = 0; ip < 2; ip++) {
            const int q0 = qt * AQ + ty * 4 + 2 * ip;
            #pragma unroll
            for (int j = 0; j < 4; j++) {
                float2 c = up2(sc2[ip][j]);
                float p0 = ex2(c.x);
                float p1 = ex2(c.y);
                if (msk) {
                    const int kg = jt * AQ + tx * 4 + j;
                    if (kg > q0)     p0 = 0.0f;
                    if (kg > q0 + 1) p1 = 0.0f;
                }
                u64 pp = pk2(p0, p1);
                add2(lsum2[ip], pp);
                *(u64*)&sPt[tx * 4 + j][ty * 4 + 2 * ip] = pp;
            }
        }
        __syncthreads();

        // ---- O += P @ V (4q x 4d per thread) ----
        #pragma unroll 8
        for (int kk = 0; kk < 64; kk++) {
            ulonglong2 pa = *(ulonglong2*)&sPt[kk][ty * 4];
            u64 ap[2] = { pa.x, pa.y };
            float4 vv = *(float4*)&sV[kk][tx * 4];
            float vr[4] = { vv.x, vv.y, vv.z, vv.w };
            #pragma unroll
            for (int j = 0; j < 4; j++) {
                u64 vs = pk2(vr[j], vr[j]);
                #pragma unroll
                for (int ip = 0; ip < 2; ip++) fma2(o2[ip][j], ap[ip], vs);
            }
        }
    }

    // ---- final row-sum reduction across the 16 tx lanes ----
    #pragma unroll
    for (int ip = 0; ip < 2; ip++) {
        float2 c = up2(lsum2[ip]);
        float s0 = c.x, s1 = c.y;
        #pragma unroll
        for (int off = 8; off; off >>= 1) {
            s0 += __shfl_xor_sync(0xffffffffu, s0, off);
            s1 += __shfl_xor_sync(0xffffffffu, s1, off);
        }
        const float inv0 = 1.0f / s0;
        const float inv1 = 1.0f / s1;
        const int r0 = qt * AQ + ty * 4 + 2 * ip;
        float2 c0 = up2(o2[ip][0]), c1 = up2(o2[ip][1]);
        float2 c2 = up2(o2[ip][2]), c3 = up2(o2[ip][3]);
        float4 r0v = make_float4(c0.x * inv0, c1.x * inv0, c2.x * inv0, c3.x * inv0);
        float4 r1v = make_float4(c0.y * inv1, c1.y * inv1, c2.y * inv1, c3.y * inv1);
        *(float4*)(Oo + ((size_t)(b_ * SS + r0)) * DD + h_ * HDIM + tx * 4) = r0v;
        *(float4*)(Oo + ((size_t)(b_ * SS + r0 + 1)) * DD + h_ * HDIM + tx * 4) = r1v;
    }
}

// ---------------------------------------------------------------------------
// Launch
// ---------------------------------------------------------------------------
extern "C" void kernel_launch(void* const* d_in, const int* in_sizes, int n_in,
                              void* d_out, int out_size)
{
    (void)n_in; (void)in_sizes; (void)out_size;

    const float* x  = (const float*)d_in[0];
    const float* wq = (const float*)d_in[2];
    const float* bq = (const float*)d_in[3];
    const float* wk = (const float*)d_in[4];
    const float* bk = (const float*)d_in[5];
    const float* wv = (const float*)d_in[6];
    const float* bv = (const float*)d_in[7];
    const float* wo = (const float*)d_in[8];
    const float* bo = (const float*)d_in[9];
    float* out = (float*)d_out;

    static float *q = nullptr, *k, *v, *att;
    if (!q) {
        cudaGetSymbolAddress((void**)&q,   g_q);
        cudaGetSymbolAddress((void**)&k,   g_k);
        cudaGetSymbolAddress((void**)&v,   g_v);
        cudaGetSymbolAddress((void**)&att, g_att);
        cudaFuncSetAttribute(attn_f2,
            cudaFuncAttributeMaxDynamicSharedMemorySize, ATTN_SMEM);
    }

    // Fused QKV projection: BN=128, 32 x 18 = 576 CTAs (1.95 waves)
    dim3 gq(NT / TM, 3 * (DD / 128));
    gemm3t<128><<<gq, 256>>>(x, wq, wk, wv, bq, bk, bv, q, k, v);

    // Attention: AQ=64 tiles, 32 x 24 = 768 CTAs, 3 CTAs/SM
    dim3 ag(SS / AQ, NBH);
    attn_f2<<<ag, 256, ATTN_SMEM>>>(q, k, v, att);

    // Output projection: BN=64, 32 x 12 = 384 CTAs (1.3 waves)
    dim3 go(NT / TM, DD / 64);
    gemm3t<64><<<go, 256>>>(att, wo, wo, wo, bo, bo, bo, out, out, out);
}

// round 15
// speedup vs baseline: 1.0034x; 1.0034x over previous
#include <cuda_runtime.h>
#include <math.h>
#include <stdint.h>

// Problem constants
#define BB 2
#define SS 2048
#define DD 768
#define HH 12
#define HDIM 64
#define NT (BB*SS)      // 4096 tokens
#define NBH (BB*HH)     // 24

typedef unsigned long long u64;

// ---------------------------------------------------------------------------
// f32x2 packed helpers
// ---------------------------------------------------------------------------
__device__ __forceinline__ u64 pk2(float lo, float hi) {
    u64 r; asm("mov.b64 %0, {%1, %2};" : "=l"(r) : "f"(lo), "f"(hi)); return r;
}
__device__ __forceinline__ float2 up2(u64 v) {
    float lo, hi; asm("mov.b64 {%0, %1}, %2;" : "=f"(lo), "=f"(hi) : "l"(v));
    return make_float2(lo, hi);
}
__device__ __forceinline__ void fma2(u64& d, u64 a, u64 b) {
    asm("fma.rn.f32x2 %0, %1, %2, %0;" : "+l"(d) : "l"(a), "l"(b));
}
__device__ __forceinline__ void add2(u64& d, u64 a) {
    asm("add.rn.f32x2 %0, %0, %1;" : "+l"(d) : "l"(a));
}
__device__ __forceinline__ float ex2(float x) {
    float r; asm("ex2.approx.f32 %0, %1;" : "=f"(r) : "f"(x)); return r;
}

// ---------------------------------------------------------------------------
// Device scratch
// ---------------------------------------------------------------------------
__device__ float g_q[(size_t)NT * DD];        // [b,s,d]
__device__ float g_k[(size_t)NT * DD];
__device__ float g_v[(size_t)NT * DD];
__device__ float g_att[(size_t)NT * DD];

#define TKK 16
#define NKT (DD / TKK)         // 48
#define TM 128

// ---------------------------------------------------------------------------
// GEMM (fused-3), templated on tile-N (FROZEN — proven optimal round 6/13).
// ---------------------------------------------------------------------------
template<int BN>
__global__ __launch_bounds__(256, 2)
void gemm3t(const float* __restrict__ A,
            const float* __restrict__ w0, const float* __restrict__ w1,
            const float* __restrict__ w2,
            const float* __restrict__ b0, const float* __restrict__ b1,
            const float* __restrict__ b2,
            float* __restrict__ o0, float* __restrict__ o1,
            float* __restrict__ o2)
{
    constexpr int NB   = DD / BN;
    constexpr int BPAD = BN + 4;
    constexpr int NJ   = BN / 32;
    constexpr int NLB  = BN / 64;
    constexpr int NCT  = BN / 16;

    __shared__ __align__(16) float sA[2][TKK][132];
    __shared__ __align__(16) float sB[2][TKK][BPAD];

    const int sel = blockIdx.y / NB;
    const float* W    = (sel == 0) ? w0 : (sel == 1) ? w1 : w2;
    const float* bias = (sel == 0) ? b0 : (sel == 1) ? b1 : b2;
    float* out        = (sel == 0) ? o0 : (sel == 1) ? o1 : o2;

    const int tid = threadIdx.x;
    const int tx = tid & 15;
    const int ty = tid >> 4;
    const int m0 = blockIdx.x * TM;
    const int n0 = (blockIdx.y % NB) * BN;

    const int i0 = tid * 2, i1 = tid * 2 + 1;
    const int ar  = i0 >> 2;
    const int ak0 = (i0 & 3) << 2;
    const int ak1 = (i1 & 3) << 2;
    int bk[NLB], bc[NLB];
    #pragma unroll
    for (int t = 0; t < NLB; t++) {
        const int idx = tid + t * 256;
        bk[t] = idx / (BN / 4);
        bc[t] = (idx % (BN / 4)) * 4;
    }

    u64 acc[8][NJ];
    #pragma unroll
    for (int i = 0; i < 8; i++)
        #pragma unroll
        for (int j = 0; j < NJ; j++) acc[i][j] = 0ull;

    float4 pa0 = *(const float4*)(A + (size_t)(m0 + ar) * DD + ak0);
    float4 pa1 = *(const float4*)(A + (size_t)(m0 + ar) * DD + ak1);
    float4 pb[NLB];
    #pragma unroll
    for (int t = 0; t < NLB; t++)
        pb[t] = *(const float4*)(W + (size_t)bk[t] * DD + n0 + bc[t]);

    sA[0][ak0 + 0][ar] = pa0.x; sA[0][ak0 + 1][ar] = pa0.y;
    sA[0][ak0 + 2][ar] = pa0.z; sA[0][ak0 + 3][ar] = pa0.w;
    sA[0][ak1 + 0][ar] = pa1.x; sA[0][ak1 + 1][ar] = pa1.y;
    sA[0][ak1 + 2][ar] = pa1.z; sA[0][ak1 + 3][ar] = pa1.w;
    #pragma unroll
    for (int t = 0; t < NLB; t++)
        *(float4*)&sB[0][bk[t]][bc[t]] = pb[t];

    for (int kt = 0; kt < NKT; kt++) {
        const int cur = kt & 1;
        if (kt + 1 < NKT) {
            const int k0 = (kt + 1) * TKK;
            pa0 = *(const float4*)(A + (size_t)(m0 + ar) * DD + k0 + ak0);
            pa1 = *(const float4*)(A + (size_t)(m0 + ar) * DD + k0 + ak1);
            #pragma unroll
            for (int t = 0; t < NLB; t++)
                pb[t] = *(const float4*)(W + (size_t)(k0 + bk[t]) * DD + n0 + bc[t]);
        }
        __syncthreads();

        #pragma unroll
        for (int kk = 0; kk < TKK; kk++) {
            float4 a0 = *(float4*)&sA[cur][kk][ty * 8];
            float4 a1 = *(float4*)&sA[cur][kk][ty * 8 + 4];
            u64 bp[NJ];
            #pragma unroll
            for (int g = 0; g < NJ / 2; g++) {
                ulonglong2 bq = *(ulonglong2*)&sB[cur][kk][tx * NCT + g * 4];
                bp[2 * g] = bq.x; bp[2 * g + 1] = bq.y;
            }
            float av[8] = { a0.x, a0.y, a0.z, a0.w, a1.x, a1.y, a1.z, a1.w };
            #pragma unroll
            for (int i = 0; i < 8; i++) {
                u64 as = pk2(av[i], av[i]);
                #pragma unroll
                for (int j = 0; j < NJ; j++) fma2(acc[i][j], as, bp[j]);
            }
        }

        if (kt + 1 < NKT) {
            const int nxt = cur ^ 1;
            sA[nxt][ak0 + 0][ar] = pa0.x; sA[nxt][ak0 + 1][ar] = pa0.y;
            sA[nxt][ak0 + 2][ar] = pa0.z; sA[nxt][ak0 + 3][ar] = pa0.w;
            sA[nxt][ak1 + 0][ar] = pa1.x; sA[nxt][ak1 + 1][ar] = pa1.y;
            sA[nxt][ak1 + 2][ar] = pa1.z; sA[nxt][ak1 + 3][ar] = pa1.w;
            #pragma unroll
            for (int t = 0; t < NLB; t++)
                *(float4*)&sB[nxt][bk[t]][bc[t]] = pb[t];
        }
    }

    #pragma unroll
    for (int i = 0; i < 8; i++) {
        float* dst = out + (size_t)(m0 + ty * 8 + i) * DD + n0 + tx * NCT;
        #pragma unroll
        for (int g = 0; g < NJ / 2; g++) {
            float4 bv = *(const float4*)(bias + n0 + tx * NCT + g * 4);
            float2 cl = up2(acc[i][2 * g]);
            float2 ch = up2(acc[i][2 * g + 1]);
            float4 o4 = make_float4(cl.x + bv.x, cl.y + bv.y,
                                    ch.x + bv.z, ch.y + bv.w);
            *(float4*)(dst + g * 4) = o4;
        }
    }
}

// ---------------------------------------------------------------------------
// FFMA2 flash attention, causal, fp32, no-max + ex2 (round-13 proven shape:
// AQ=128 x AK=64, 2 CTAs/SM) + SOFTWARE-PIPELINED K/V global loads: LDG for
// tile jt+1 issues right after tile jt's post-load barrier, so L2 latency is
// covered by the QK/exp/PV compute phase; only STS remains between barriers.
// ---------------------------------------------------------------------------
#define AQ 128
#define AK 64
#define QP 132
#define KP 68
#define ATTN_SMEM ((64*QP + 2*64*KP + 64*QP) * 4)   // 102400 B
#define QSCL 0.18033688f   // 0.125 * log2(e)

__global__ __launch_bounds__(256, 2)
void attn_f2(const float* __restrict__ Q, const float* __restrict__ K,
             const float* __restrict__ V, float* __restrict__ Oo)
{
    extern __shared__ __align__(16) float sm[];
    float (*sQt)[QP] = (float(*)[QP])(sm);                         // [d][qrow]
    float (*sKt)[KP] = (float(*)[KP])(sm + 64 * QP);               // [d][kcol]
    float (*sV )[KP] = (float(*)[KP])(sm + 64 * QP + 64 * KP);     // [k][d]
    float (*sPt)[QP] = (float(*)[QP])(sm + 64 * QP + 2 * 64 * KP); // [k][qrow]

    const int tid = threadIdx.x;
    const int tx = tid & 15;
    const int ty = tid >> 4;
    const int qt = (SS / AQ - 1) - blockIdx.x;   // heavy tiles first
    const int bh = blockIdx.y;
    const int b_ = bh / HH, h_ = bh % HH;

    const float* Qb = Q + (size_t)b_ * SS * DD + h_ * HDIM;
    const float* Kb = K + (size_t)b_ * SS * DD + h_ * HDIM;
    const float* Vb = V + (size_t)b_ * SS * DD + h_ * HDIM;

    // Load Q transposed, pre-scaled into ex2 units
    #pragma unroll
    for (int l = 0; l < 8; l++) {
        const int idx = tid + l * 256;
        const int r = idx >> 4, d0 = (idx & 15) << 2;
        float4 v4 = *(const float4*)(Qb + (size_t)(qt * AQ + r) * DD + d0);
        sQt[d0 + 0][r] = v4.x * QSCL; sQt[d0 + 1][r] = v4.y * QSCL;
        sQt[d0 + 2][r] = v4.z * QSCL; sQt[d0 + 3][r] = v4.w * QSCL;
    }

    u64 lsum2[4];
    u64 o2[4][4];
    #pragma unroll
    for (int ip = 0; ip < 4; ip++) {
        lsum2[ip] = 0ull;
        #pragma unroll
        for (int j = 0; j < 4; j++) o2[ip][j] = 0ull;
    }

    // K/V load mapping (per l): row r = ty + 16*l, cols d0 = tx*4
    // Prefetch tile 0 into registers
    float4 pk[4], pv[4];
    #pragma unroll
    for (int l = 0; l < 4; l++) {
        const int r = ty + 16 * l;
        pk[l] = *(const float4*)(Kb + (size_t)r * DD + tx * 4);
        pv[l] = *(const float4*)(Vb + (size_t)r * DD + tx * 4);
    }

    const int njt = 2 * qt + 2;
    for (int jt = 0; jt < njt; jt++) {
        __syncthreads();   // prev PV done -> sKt/sV free
        // Store prefetched K (transposed) and V
        #pragma unroll
        for (int l = 0; l < 4; l++) {
            const int r = ty + 16 * l;
            const int d0 = tx * 4;
            sKt[d0 + 0][r] = pk[l].x; sKt[d0 + 1][r] = pk[l].y;
            sKt[d0 + 2][r] = pk[l].z; sKt[d0 + 3][r] = pk[l].w;
            *(float4*)&sV[r][d0] = pv[l];
        }
        __syncthreads();

        // Issue LDG for tile jt+1 (covered by compute below)
        if (jt + 1 < njt) {
            #pragma unroll
            for (int l = 0; l < 4; l++) {
                const int r = (jt + 1) * AK + ty + 16 * l;
                pk[l] = *(const float4*)(Kb + (size_t)r * DD + tx * 4);
                pv[l] = *(const float4*)(Vb + (size_t)r * DD + tx * 4);
            }
        }

        // Last tail tile: fully-masked warps skip compute
        const bool skip = (jt == 2 * qt + 1) && (ty < 8);
        if (!skip) {
            // ---- QK scores (packed pairs of q-rows), ex2 units ----
            u64 sc2[4][4];
            #pragma unroll
            for (int ip = 0; ip < 4; ip++)
                #pragma unroll
                for (int j = 0; j < 4; j++) sc2[ip][j] = 0ull;

            #pragma unroll 8
            for (int dd = 0; dd < 64; dd++) {
                ulonglong2 qa = *(ulonglong2*)&sQt[dd][ty * 8];
                ulonglong2 qb = *(ulonglong2*)&sQt[dd][ty * 8 + 4];
                u64 ap[4] = { qa.x, qa.y, qb.x, qb.y };
                float4 kv = *(float4*)&sKt[dd][tx * 4];
                float kr[4] = { kv.x, kv.y, kv.z, kv.w };
                #pragma unroll
                for (int j = 0; j < 4; j++) {
                    u64 ks = pk2(kr[j], kr[j]);
                    #pragma unroll
                    for (int ip = 0; ip < 4; ip++) fma2(sc2[ip][j], ap[ip], ks);
                }
            }

            // ---- p = ex2(score); masked -> 0 ----
            const bool msk = (jt == 2 * qt) ? (ty < 8) : (jt == 2 * qt + 1);
            #pragma unroll
            for (int ip = 0; ip < 4; ip++) {
                const int q0 = qt * AQ + ty * 8 + 2 * ip;
                #pragma unroll
                for (int j = 0; j < 4; j++) {
                    float2 c = up2(sc2[ip][j]);
                    float p0 = ex2(c.x);
                    float p1 = ex2(c.y);
                    if (msk) {
                        const int kg = jt * AK + tx * 4 + j;
                        if (kg > q0)     p0 = 0.0f;
                        if (kg > q0 + 1) p1 = 0.0f;
                    }
                    u64 pp = pk2(p0, p1);
                    add2(lsum2[ip], pp);
                    *(u64*)&sPt[tx * 4 + j][ty * 8 + 2 * ip] = pp;
                }
            }
        }
        __syncthreads();

        if (!skip) {
            // ---- O += P @ V ----
            #pragma unroll 8
            for (int kk = 0; kk < 64; kk++) {
                ulonglong2 pa = *(ulonglong2*)&sPt[kk][ty * 8];
                ulonglong2 pb = *(ulonglong2*)&sPt[kk][ty * 8 + 4];
                u64 ap[4] = { pa.x, pa.y, pb.x, pb.y };
                float4 vv = *(float4*)&sV[kk][tx * 4];
                float vr[4] = { vv.x, vv.y, vv.z, vv.w };
                #pragma unroll
                for (int j = 0; j < 4; j++) {
                    u64 vs = pk2(vr[j], vr[j]);
                    #pragma unroll
                    for (int ip = 0; ip < 4; ip++) fma2(o2[ip][j], ap[ip], vs);
                }
            }
        }
    }

    // ---- single final reduction of row sums across the 16 tx lanes ----
    #pragma unroll
    for (int ip = 0; ip < 4; ip++) {
        float2 c = up2(lsum2[ip]);
        float s0 = c.x, s1 = c.y;
        #pragma unroll
        for (int off = 8; off; off >>= 1) {
            s0 += __shfl_xor_sync(0xffffffffu, s0, off);
            s1 += __shfl_xor_sync(0xffffffffu, s1, off);
        }
        const float inv0 = 1.0f / s0;
        const float inv1 = 1.0f / s1;
        const int r0 = qt * AQ + ty * 8 + 2 * ip;
        float2 c0 = up2(o2[ip][0]), c1 = up2(o2[ip][1]);
        float2 c2 = up2(o2[ip][2]), c3 = up2(o2[ip][3]);
        float4 r0v = make_float4(c0.x * inv0, c1.x * inv0, c2.x * inv0, c3.x * inv0);
        float4 r1v = make_float4(c0.y * inv1, c1.y * inv1, c2.y * inv1, c3.y * inv1);
        *(float4*)(Oo + ((size_t)(b_ * SS + r0)) * DD + h_ * HDIM + tx * 4) = r0v;
        *(float4*)(Oo + ((size_t)(b_ * SS + r0 + 1)) * DD + h_ * HDIM + tx * 4) = r1v;
    }
}

// ---------------------------------------------------------------------------
// Launch
// ---------------------------------------------------------------------------
extern "C" void kernel_launch(void* const* d_in, const int* in_sizes, int n_in,
                              void* d_out, int out_size)
{
    (void)n_in; (void)in_sizes; (void)out_size;

    const float* x  = (const float*)d_in[0];
    const float* wq = (const float*)d_in[2];
    const float* bq = (const float*)d_in[3];
    const float* wk = (const float*)d_in[4];
    const float* bk = (const float*)d_in[5];
    const float* wv = (const float*)d_in[6];
    const float* bv = (const float*)d_in[7];
    const float* wo = (const float*)d_in[8];
    const float* bo = (const float*)d_in[9];
    float* out = (float*)d_out;

    static float *q = nullptr, *k, *v, *att;
    if (!q) {
        cudaGetSymbolAddress((void**)&q,   g_q);
        cudaGetSymbolAddress((void**)&k,   g_k);
        cudaGetSymbolAddress((void**)&v,   g_v);
        cudaGetSymbolAddress((void**)&att, g_att);
        cudaFuncSetAttribute(attn_f2,
            cudaFuncAttributeMaxDynamicSharedMemorySize, ATTN_SMEM);
    }

    // Fused QKV projection: BN=128, 32 x 18 = 576 CTAs (1.95 waves)
    dim3 gq(NT / TM, 3 * (DD / 128));
    gemm3t<128><<<gq, 256>>>(x, wq, wk, wv, bq, bk, bv, q, k, v);

    // Attention: AQ=128 tiles, pipelined K/V loads, 16 x 24 CTAs
    dim3 ag(SS / AQ, NBH);
    attn_f2<<<ag, 256, ATTN_SMEM>>>(q, k, v, att);

    // Output projection: BN=64, 32 x 12 = 384 CTAs (1.3 waves)
    dim3 go(NT / TM, DD / 64);
    gemm3t<64><<<go, 256>>>(att, wo, wo, wo, bo, bo, bo, out, out, out);
}

// round 16
// speedup vs baseline: 1.0427x; 1.0392x over previous
#include <cuda_runtime.h>
#include <math.h>
#include <stdint.h>

// Problem constants
#define BB 2
#define SS 2048
#define DD 768
#define HH 12
#define HDIM 64
#define NT (BB*SS)      // 4096 tokens
#define NBH (BB*HH)     // 24

typedef unsigned long long u64;

// ---------------------------------------------------------------------------
// f32x2 packed helpers
// ---------------------------------------------------------------------------
__device__ __forceinline__ u64 pk2(float lo, float hi) {
    u64 r; asm("mov.b64 %0, {%1, %2};" : "=l"(r) : "f"(lo), "f"(hi)); return r;
}
__device__ __forceinline__ float2 up2(u64 v) {
    float lo, hi; asm("mov.b64 {%0, %1}, %2;" : "=f"(lo), "=f"(hi) : "l"(v));
    return make_float2(lo, hi);
}
__device__ __forceinline__ void fma2(u64& d, u64 a, u64 b) {
    asm("fma.rn.f32x2 %0, %1, %2, %0;" : "+l"(d) : "l"(a), "l"(b));
}
__device__ __forceinline__ void add2(u64& d, u64 a) {
    asm("add.rn.f32x2 %0, %0, %1;" : "+l"(d) : "l"(a));
}
__device__ __forceinline__ float ex2(float x) {
    float r; asm("ex2.approx.f32 %0, %1;" : "=f"(r) : "f"(x)); return r;
}

// ---------------------------------------------------------------------------
// Device scratch
// ---------------------------------------------------------------------------
__device__ float g_q[(size_t)NT * DD];        // [b,s,d]
__device__ float g_k[(size_t)NT * DD];
__device__ float g_v[(size_t)NT * DD];
__device__ float g_att[(size_t)NT * DD];

#define TKK 16
#define NKT (DD / TKK)         // 48
#define TM 128

// ---------------------------------------------------------------------------
// GEMM (fused-3), templated on tile-N (FROZEN — proven optimal round 6/13).
// ---------------------------------------------------------------------------
template<int BN>
__global__ __launch_bounds__(256, 2)
void gemm3t(const float* __restrict__ A,
            const float* __restrict__ w0, const float* __restrict__ w1,
            const float* __restrict__ w2,
            const float* __restrict__ b0, const float* __restrict__ b1,
            const float* __restrict__ b2,
            float* __restrict__ o0, float* __restrict__ o1,
            float* __restrict__ o2)
{
    constexpr int NB   = DD / BN;
    constexpr int BPAD = BN + 4;
    constexpr int NJ   = BN / 32;
    constexpr int NLB  = BN / 64;
    constexpr int NCT  = BN / 16;

    __shared__ __align__(16) float sA[2][TKK][132];
    __shared__ __align__(16) float sB[2][TKK][BPAD];

    const int sel = blockIdx.y / NB;
    const float* W    = (sel == 0) ? w0 : (sel == 1) ? w1 : w2;
    const float* bias = (sel == 0) ? b0 : (sel == 1) ? b1 : b2;
    float* out        = (sel == 0) ? o0 : (sel == 1) ? o1 : o2;

    const int tid = threadIdx.x;
    const int tx = tid & 15;
    const int ty = tid >> 4;
    const int m0 = blockIdx.x * TM;
    const int n0 = (blockIdx.y % NB) * BN;

    const int i0 = tid * 2, i1 = tid * 2 + 1;
    const int ar  = i0 >> 2;
    const int ak0 = (i0 & 3) << 2;
    const int ak1 = (i1 & 3) << 2;
    int bk[NLB], bc[NLB];
    #pragma unroll
    for (int t = 0; t < NLB; t++) {
        const int idx = tid + t * 256;
        bk[t] = idx / (BN / 4);
        bc[t] = (idx % (BN / 4)) * 4;
    }

    u64 acc[8][NJ];
    #pragma unroll
    for (int i = 0; i < 8; i++)
        #pragma unroll
        for (int j = 0; j < NJ; j++) acc[i][j] = 0ull;

    float4 pa0 = *(const float4*)(A + (size_t)(m0 + ar) * DD + ak0);
    float4 pa1 = *(const float4*)(A + (size_t)(m0 + ar) * DD + ak1);
    float4 pb[NLB];
    #pragma unroll
    for (int t = 0; t < NLB; t++)
        pb[t] = *(const float4*)(W + (size_t)bk[t] * DD + n0 + bc[t]);

    sA[0][ak0 + 0][ar] = pa0.x; sA[0][ak0 + 1][ar] = pa0.y;
    sA[0][ak0 + 2][ar] = pa0.z; sA[0][ak0 + 3][ar] = pa0.w;
    sA[0][ak1 + 0][ar] = pa1.x; sA[0][ak1 + 1][ar] = pa1.y;
    sA[0][ak1 + 2][ar] = pa1.z; sA[0][ak1 + 3][ar] = pa1.w;
    #pragma unroll
    for (int t = 0; t < NLB; t++)
        *(float4*)&sB[0][bk[t]][bc[t]] = pb[t];

    for (int kt = 0; kt < NKT; kt++) {
        const int cur = kt & 1;
        if (kt + 1 < NKT) {
            const int k0 = (kt + 1) * TKK;
            pa0 = *(const float4*)(A + (size_t)(m0 + ar) * DD + k0 + ak0);
            pa1 = *(const float4*)(A + (size_t)(m0 + ar) * DD + k0 + ak1);
            #pragma unroll
            for (int t = 0; t < NLB; t++)
                pb[t] = *(const float4*)(W + (size_t)(k0 + bk[t]) * DD + n0 + bc[t]);
        }
        __syncthreads();

        #pragma unroll
        for (int kk = 0; kk < TKK; kk++) {
            float4 a0 = *(float4*)&sA[cur][kk][ty * 8];
            float4 a1 = *(float4*)&sA[cur][kk][ty * 8 + 4];
            u64 bp[NJ];
            #pragma unroll
            for (int g = 0; g < NJ / 2; g++) {
                ulonglong2 bq = *(ulonglong2*)&sB[cur][kk][tx * NCT + g * 4];
                bp[2 * g] = bq.x; bp[2 * g + 1] = bq.y;
            }
            float av[8] = { a0.x, a0.y, a0.z, a0.w, a1.x, a1.y, a1.z, a1.w };
            #pragma unroll
            for (int i = 0; i < 8; i++) {
                u64 as = pk2(av[i], av[i]);
                #pragma unroll
                for (int j = 0; j < NJ; j++) fma2(acc[i][j], as, bp[j]);
            }
        }

        if (kt + 1 < NKT) {
            const int nxt = cur ^ 1;
            sA[nxt][ak0 + 0][ar] = pa0.x; sA[nxt][ak0 + 1][ar] = pa0.y;
            sA[nxt][ak0 + 2][ar] = pa0.z; sA[nxt][ak0 + 3][ar] = pa0.w;
            sA[nxt][ak1 + 0][ar] = pa1.x; sA[nxt][ak1 + 1][ar] = pa1.y;
            sA[nxt][ak1 + 2][ar] = pa1.z; sA[nxt][ak1 + 3][ar] = pa1.w;
            #pragma unroll
            for (int t = 0; t < NLB; t++)
                *(float4*)&sB[nxt][bk[t]][bc[t]] = pb[t];
        }
    }

    #pragma unroll
    for (int i = 0; i < 8; i++) {
        float* dst = out + (size_t)(m0 + ty * 8 + i) * DD + n0 + tx * NCT;
        #pragma unroll
        for (int g = 0; g < NJ / 2; g++) {
            float4 bv = *(const float4*)(bias + n0 + tx * NCT + g * 4);
            float2 cl = up2(acc[i][2 * g]);
            float2 ch = up2(acc[i][2 * g + 1]);
            float4 o4 = make_float4(cl.x + bv.x, cl.y + bv.y,
                                    ch.x + bv.z, ch.y + bv.w);
            *(float4*)(dst + g * 4) = o4;
        }
    }
}

// ---------------------------------------------------------------------------
// FFMA2 flash attention, causal, fp32, no-max + ex2.
// AQ=256 x AK=64, 512 threads, 1 CTA/SM (16 warps, same as 2x256 before but
// the heaviest CTA owns its SM; K/V loads+stores+barriers per unit work
// halved; ty-granular skipping over 4 diagonal tiles).
// Per-thread body identical to the proven round-13 kernel.
// ---------------------------------------------------------------------------
#define AQ 256
#define AK 64
#define QP 260
#define KP 68
#define ATTN_SMEM ((64*QP + 2*64*KP + 64*QP) * 4)   // 167936 B
#define QSCL 0.18033688f   // 0.125 * log2(e)

__global__ __launch_bounds__(512, 1)
void attn_f2(const float* __restrict__ Q, const float* __restrict__ K,
             const float* __restrict__ V, float* __restrict__ Oo)
{
    extern __shared__ __align__(16) float sm[];
    float (*sQt)[QP] = (float(*)[QP])(sm);                         // [d][qrow]
    float (*sKt)[KP] = (float(*)[KP])(sm + 64 * QP);               // [d][kcol]
    float (*sV )[KP] = (float(*)[KP])(sm + 64 * QP + 64 * KP);     // [k][d]
    float (*sPt)[QP] = (float(*)[QP])(sm + 64 * QP + 2 * 64 * KP); // [k][qrow]

    const int tid = threadIdx.x;
    const int tx = tid & 15;               // k-col / d group (4 each)
    const int ty = tid >> 4;               // q-row group (8 each), 0..31
    const int qt = (SS / AQ - 1) - blockIdx.x;   // 7..0, heavy first
    const int bh = blockIdx.y;
    const int b_ = bh / HH, h_ = bh % HH;

    const float* Qb = Q + (size_t)b_ * SS * DD + h_ * HDIM;
    const float* Kb = K + (size_t)b_ * SS * DD + h_ * HDIM;
    const float* Vb = V + (size_t)b_ * SS * DD + h_ * HDIM;

    // Load Q transposed, pre-scaled into ex2 units (8 float4 / thread)
    #pragma unroll
    for (int l = 0; l < 8; l++) {
        const int idx = tid + l * 512;
        const int r = idx >> 4, d0 = (idx & 15) << 2;
        float4 v4 = *(const float4*)(Qb + (size_t)(qt * AQ + r) * DD + d0);
        sQt[d0 + 0][r] = v4.x * QSCL; sQt[d0 + 1][r] = v4.y * QSCL;
        sQt[d0 + 2][r] = v4.z * QSCL; sQt[d0 + 3][r] = v4.w * QSCL;
    }

    u64 lsum2[4];                // packed row-sums (rows 2ip, 2ip+1)
    u64 o2[4][4];
    #pragma unroll
    for (int ip = 0; ip < 4; ip++) {
        lsum2[ip] = 0ull;
        #pragma unroll
        for (int j = 0; j < 4; j++) o2[ip][j] = 0ull;
    }

    const int njt = 4 * qt + 4;
    for (int jt = 0; jt < njt; jt++) {
        __syncthreads();   // prev PV done -> sKt/sV free
        #pragma unroll
        for (int l = 0; l < 2; l++) {
            const int idx = tid + l * 512;
            const int r = idx >> 4, d0 = (idx & 15) << 2;
            float4 kv = *(const float4*)(Kb + (size_t)(jt * AK + r) * DD + d0);
            sKt[d0 + 0][r] = kv.x; sKt[d0 + 1][r] = kv.y;
            sKt[d0 + 2][r] = kv.z; sKt[d0 + 3][r] = kv.w;
            *(float4*)&sV[r][d0] =
                *(const float4*)(Vb + (size_t)(jt * AK + r) * DD + d0);
        }
        __syncthreads();

        // Diagonal-region classification (jl >= 0 only for last 4 tiles):
        //   skip: all 8 q-rows of this ty-group are below the k-range
        //   msk : k-range straddles this ty-group's q-rows
        const int jl = jt - 4 * qt;
        const bool skip = (jl >= 0) && (ty < 8 * jl);
        const bool msk  = (jl >= 0) && ((ty >> 3) == jl);

        if (!skip) {
            // ---- QK scores (packed pairs of q-rows), ex2 units ----
            u64 sc2[4][4];
            #pragma unroll
            for (int ip = 0; ip < 4; ip++)
                #pragma unroll
                for (int j = 0; j < 4; j++) sc2[ip][j] = 0ull;

            #pragma unroll 8
            for (int dd = 0; dd < 64; dd++) {
                ulonglong2 qa = *(ulonglong2*)&sQt[dd][ty * 8];
                ulonglong2 qb = *(ulonglong2*)&sQt[dd][ty * 8 + 4];
                u64 ap[4] = { qa.x, qa.y, qb.x, qb.y };
                float4 kv = *(float4*)&sKt[dd][tx * 4];
                float kr[4] = { kv.x, kv.y, kv.z, kv.w };
                #pragma unroll
                for (int j = 0; j < 4; j++) {
                    u64 ks = pk2(kr[j], kr[j]);
                    #pragma unroll
                    for (int ip = 0; ip < 4; ip++) fma2(sc2[ip][j], ap[ip], ks);
                }
            }

            // ---- p = ex2(score); masked -> 0 ----
            #pragma unroll
            for (int ip = 0; ip < 4; ip++) {
                const int q0 = qt * AQ + ty * 8 + 2 * ip;
                #pragma unroll
                for (int j = 0; j < 4; j++) {
                    float2 c = up2(sc2[ip][j]);
                    float p0 = ex2(c.x);
                    float p1 = ex2(c.y);
                    if (msk) {
                        const int kg = jt * AK + tx * 4 + j;
                        if (kg > q0)     p0 = 0.0f;
                        if (kg > q0 + 1) p1 = 0.0f;
                    }
                    u64 pp = pk2(p0, p1);
                    add2(lsum2[ip], pp);
                    *(u64*)&sPt[tx * 4 + j][ty * 8 + 2 * ip] = pp;
                }
            }
        }
        __syncthreads();

        if (!skip) {
            // ---- O += P @ V ----
            #pragma unroll 8
            for (int kk = 0; kk < 64; kk++) {
                ulonglong2 pa = *(ulonglong2*)&sPt[kk][ty * 8];
                ulonglong2 pb = *(ulonglong2*)&sPt[kk][ty * 8 + 4];
                u64 ap[4] = { pa.x, pa.y, pb.x, pb.y };
                float4 vv = *(float4*)&sV[kk][tx * 4];
                float vr[4] = { vv.x, vv.y, vv.z, vv.w };
                #pragma unroll
                for (int j = 0; j < 4; j++) {
                    u64 vs = pk2(vr[j], vr[j]);
                    #pragma unroll
                    for (int ip = 0; ip < 4; ip++) fma2(o2[ip][j], ap[ip], vs);
                }
            }
        }
    }

    // ---- single final reduction of row sums across the 16 tx lanes ----
    #pragma unroll
    for (int ip = 0; ip < 4; ip++) {
        float2 c = up2(lsum2[ip]);
        float s0 = c.x, s1 = c.y;
        #pragma unroll
        for (int off = 8; off; off >>= 1) {
            s0 += __shfl_xor_sync(0xffffffffu, s0, off);
            s1 += __shfl_xor_sync(0xffffffffu, s1, off);
        }
        const float inv0 = 1.0f / s0;
        const float inv1 = 1.0f / s1;
        const int r0 = qt * AQ + ty * 8 + 2 * ip;
        float2 c0 = up2(o2[ip][0]), c1 = up2(o2[ip][1]);
        float2 c2 = up2(o2[ip][2]), c3 = up2(o2[ip][3]);
        float4 r0v = make_float4(c0.x * inv0, c1.x * inv0, c2.x * inv0, c3.x * inv0);
        float4 r1v = make_float4(c0.y * inv1, c1.y * inv1, c2.y * inv1, c3.y * inv1);
        *(float4*)(Oo + ((size_t)(b_ * SS + r0)) * DD + h_ * HDIM + tx * 4) = r0v;
        *(float4*)(Oo + ((size_t)(b_ * SS + r0 + 1)) * DD + h_ * HDIM + tx * 4) = r1v;
    }
}

// ---------------------------------------------------------------------------
// Launch
// ---------------------------------------------------------------------------
extern "C" void kernel_launch(void* const* d_in, const int* in_sizes, int n_in,
                              void* d_out, int out_size)
{
    (void)n_in; (void)in_sizes; (void)out_size;

    const float* x  = (const float*)d_in[0];
    const float* wq = (const float*)d_in[2];
    const float* bq = (const float*)d_in[3];
    const float* wk = (const float*)d_in[4];
    const float* bk = (const float*)d_in[5];
    const float* wv = (const float*)d_in[6];
    const float* bv = (const float*)d_in[7];
    const float* wo = (const float*)d_in[8];
    const float* bo = (const float*)d_in[9];
    float* out = (float*)d_out;

    static float *q = nullptr, *k, *v, *att;
    if (!q) {
        cudaGetSymbolAddress((void**)&q,   g_q);
        cudaGetSymbolAddress((void**)&k,   g_k);
        cudaGetSymbolAddress((void**)&v,   g_v);
        cudaGetSymbolAddress((void**)&att, g_att);
        cudaFuncSetAttribute(attn_f2,
            cudaFuncAttributeMaxDynamicSharedMemorySize, ATTN_SMEM);
    }

    // Fused QKV projection: BN=128, 32 x 18 = 576 CTAs (1.95 waves)
    dim3 gq(NT / TM, 3 * (DD / 128));
    gemm3t<128><<<gq, 256>>>(x, wq, wk, wv, bq, bk, bv, q, k, v);

    // Attention: AQ=256 tiles, 8 x 24 = 192 CTAs, 1 CTA/SM, 512 threads
    dim3 ag(SS / AQ, NBH);
    attn_f2<<<ag, 512, ATTN_SMEM>>>(q, k, v, att);

    // Output projection: BN=64, 32 x 12 = 384 CTAs (1.3 waves)
    dim3 go(NT / TM, DD / 64);
    gemm3t<64><<<go, 256>>>(att, wo, wo, wo, bo, bo, bo, out, out, out);
}

// round 17
// speedup vs baseline: 1.2465x; 1.1955x over previous
#include <cuda_runtime.h>
#include <math.h>
#include <stdint.h>

// Problem constants
#define BB 2
#define SS 2048
#define DD 768
#define HH 12
#define HDIM 64
#define NT (BB*SS)      // 4096 tokens
#define NBH (BB*HH)     // 24

typedef unsigned long long u64;

// ---------------------------------------------------------------------------
// f32x2 packed helpers
// ---------------------------------------------------------------------------
__device__ __forceinline__ u64 pk2(float lo, float hi) {
    u64 r; asm("mov.b64 %0, {%1, %2};" : "=l"(r) : "f"(lo), "f"(hi)); return r;
}
__device__ __forceinline__ float2 up2(u64 v) {
    float lo, hi; asm("mov.b64 {%0, %1}, %2;" : "=f"(lo), "=f"(hi) : "l"(v));
    return make_float2(lo, hi);
}
__device__ __forceinline__ void fma2(u64& d, u64 a, u64 b) {
    asm("fma.rn.f32x2 %0, %1, %2, %0;" : "+l"(d) : "l"(a), "l"(b));
}
__device__ __forceinline__ void add2(u64& d, u64 a) {
    asm("add.rn.f32x2 %0, %0, %1;" : "+l"(d) : "l"(a));
}
__device__ __forceinline__ float ex2(float x) {
    float r; asm("ex2.approx.f32 %0, %1;" : "=f"(r) : "f"(x)); return r;
}

// ---------------------------------------------------------------------------
// Device scratch
// ---------------------------------------------------------------------------
__device__ float g_q[(size_t)NT * DD];        // [b,s,d]
__device__ float g_k[(size_t)NT * DD];
__device__ float g_v[(size_t)NT * DD];
__device__ float g_att[(size_t)NT * DD];
__device__ float g_part[(size_t)4 * NT * DD]; // split-k partial O (raw)
__device__ float g_ls[(size_t)4 * NBH * SS];  // split-k partial row sums

#define TKK 16
#define NKT (DD / TKK)         // 48
#define TM 128

// ---------------------------------------------------------------------------
// GEMM (fused-3), templated on tile-N (FROZEN — proven optimal round 6/13).
// ---------------------------------------------------------------------------
template<int BN>
__global__ __launch_bounds__(256, 2)
void gemm3t(const float* __restrict__ A,
            const float* __restrict__ w0, const float* __restrict__ w1,
            const float* __restrict__ w2,
            const float* __restrict__ b0, const float* __restrict__ b1,
            const float* __restrict__ b2,
            float* __restrict__ o0, float* __restrict__ o1,
            float* __restrict__ o2)
{
    constexpr int NB   = DD / BN;
    constexpr int BPAD = BN + 4;
    constexpr int NJ   = BN / 32;
    constexpr int NLB  = BN / 64;
    constexpr int NCT  = BN / 16;

    __shared__ __align__(16) float sA[2][TKK][132];
    __shared__ __align__(16) float sB[2][TKK][BPAD];

    const int sel = blockIdx.y / NB;
    const float* W    = (sel == 0) ? w0 : (sel == 1) ? w1 : w2;
    const float* bias = (sel == 0) ? b0 : (sel == 1) ? b1 : b2;
    float* out        = (sel == 0) ? o0 : (sel == 1) ? o1 : o2;

    const int tid = threadIdx.x;
    const int tx = tid & 15;
    const int ty = tid >> 4;
    const int m0 = blockIdx.x * TM;
    const int n0 = (blockIdx.y % NB) * BN;

    const int i0 = tid * 2, i1 = tid * 2 + 1;
    const int ar  = i0 >> 2;
    const int ak0 = (i0 & 3) << 2;
    const int ak1 = (i1 & 3) << 2;
    int bk[NLB], bc[NLB];
    #pragma unroll
    for (int t = 0; t < NLB; t++) {
        const int idx = tid + t * 256;
        bk[t] = idx / (BN / 4);
        bc[t] = (idx % (BN / 4)) * 4;
    }

    u64 acc[8][NJ];
    #pragma unroll
    for (int i = 0; i < 8; i++)
        #pragma unroll
        for (int j = 0; j < NJ; j++) acc[i][j] = 0ull;

    float4 pa0 = *(const float4*)(A + (size_t)(m0 + ar) * DD + ak0);
    float4 pa1 = *(const float4*)(A + (size_t)(m0 + ar) * DD + ak1);
    float4 pb[NLB];
    #pragma unroll
    for (int t = 0; t < NLB; t++)
        pb[t] = *(const float4*)(W + (size_t)bk[t] * DD + n0 + bc[t]);

    sA[0][ak0 + 0][ar] = pa0.x; sA[0][ak0 + 1][ar] = pa0.y;
    sA[0][ak0 + 2][ar] = pa0.z; sA[0][ak0 + 3][ar] = pa0.w;
    sA[0][ak1 + 0][ar] = pa1.x; sA[0][ak1 + 1][ar] = pa1.y;
    sA[0][ak1 + 2][ar] = pa1.z; sA[0][ak1 + 3][ar] = pa1.w;
    #pragma unroll
    for (int t = 0; t < NLB; t++)
        *(float4*)&sB[0][bk[t]][bc[t]] = pb[t];

    for (int kt = 0; kt < NKT; kt++) {
        const int cur = kt & 1;
        if (kt + 1 < NKT) {
            const int k0 = (kt + 1) * TKK;
            pa0 = *(const float4*)(A + (size_t)(m0 + ar) * DD + k0 + ak0);
            pa1 = *(const float4*)(A + (size_t)(m0 + ar) * DD + k0 + ak1);
            #pragma unroll
            for (int t = 0; t < NLB; t++)
                pb[t] = *(const float4*)(W + (size_t)(k0 + bk[t]) * DD + n0 + bc[t]);
        }
        __syncthreads();

        #pragma unroll
        for (int kk = 0; kk < TKK; kk++) {
            float4 a0 = *(float4*)&sA[cur][kk][ty * 8];
            float4 a1 = *(float4*)&sA[cur][kk][ty * 8 + 4];
            u64 bp[NJ];
            #pragma unroll
            for (int g = 0; g < NJ / 2; g++) {
                ulonglong2 bq = *(ulonglong2*)&sB[cur][kk][tx * NCT + g * 4];
                bp[2 * g] = bq.x; bp[2 * g + 1] = bq.y;
            }
            float av[8] = { a0.x, a0.y, a0.z, a0.w, a1.x, a1.y, a1.z, a1.w };
            #pragma unroll
            for (int i = 0; i < 8; i++) {
                u64 as = pk2(av[i], av[i]);
                #pragma unroll
                for (int j = 0; j < NJ; j++) fma2(acc[i][j], as, bp[j]);
            }
        }

        if (kt + 1 < NKT) {
            const int nxt = cur ^ 1;
            sA[nxt][ak0 + 0][ar] = pa0.x; sA[nxt][ak0 + 1][ar] = pa0.y;
            sA[nxt][ak0 + 2][ar] = pa0.z; sA[nxt][ak0 + 3][ar] = pa0.w;
            sA[nxt][ak1 + 0][ar] = pa1.x; sA[nxt][ak1 + 1][ar] = pa1.y;
            sA[nxt][ak1 + 2][ar] = pa1.z; sA[nxt][ak1 + 3][ar] = pa1.w;
            #pragma unroll
            for (int t = 0; t < NLB; t++)
                *(float4*)&sB[nxt][bk[t]][bc[t]] = pb[t];
        }
    }

    #pragma unroll
    for (int i = 0; i < 8; i++) {
        float* dst = out + (size_t)(m0 + ty * 8 + i) * DD + n0 + tx * NCT;
        #pragma unroll
        for (int g = 0; g < NJ / 2; g++) {
            float4 bv = *(const float4*)(bias + n0 + tx * NCT + g * 4);
            float2 cl = up2(acc[i][2 * g]);
            float2 ch = up2(acc[i][2 * g + 1]);
            float4 o4 = make_float4(cl.x + bv.x, cl.y + bv.y,
                                    ch.x + bv.z, ch.y + bv.w);
            *(float4*)(dst + g * 4) = o4;
        }
    }
}

// ---------------------------------------------------------------------------
// FFMA2 flash attention, SPLIT-K over k-tiles (legal because no-max softmax
// partials over disjoint k-ranges combine by plain addition).
// Per-bh work = 40 uniform chunks of <=8 jt-tiles; grid 960 CTAs.
// Tile body identical to the proven round-13 kernel (AQ=128 x AK=64).
// Each chunk writes RAW (unnormalized) O and its row-sum into partial planes.
// ---------------------------------------------------------------------------
#define AQ 128
#define AK 64
#define QP 132
#define KP 68
#define ATTN_SMEM ((64*QP + 2*64*KP + 64*QP) * 4)   // 102400 B
#define QSCL 0.18033688f   // 0.125 * log2(e)
#define NCHUNK 40          // sum over qt of ceil((2qt+2)/8)

__global__ __launch_bounds__(256, 2)
void attn_f2(const float* __restrict__ Q, const float* __restrict__ K,
             const float* __restrict__ V,
             float* __restrict__ part, float* __restrict__ lsg)
{
    extern __shared__ __align__(16) float sm[];
    float (*sQt)[QP] = (float(*)[QP])(sm);                         // [d][qrow]
    float (*sKt)[KP] = (float(*)[KP])(sm + 64 * QP);               // [d][kcol]
    float (*sV )[KP] = (float(*)[KP])(sm + 64 * QP + 64 * KP);     // [k][d]
    float (*sPt)[QP] = (float(*)[QP])(sm + 64 * QP + 2 * 64 * KP); // [k][qrow]

    const int tid = threadIdx.x;
    const int tx = tid & 15;
    const int ty = tid >> 4;
    const int bh = blockIdx.y;
    const int b_ = bh / HH, h_ = bh % HH;

    // Resolve chunk id -> (qt, c); qt descending => heavy chunks first
    int qt = 15, cch = 0;
    {
        const int cid = blockIdx.x;
        int accu = 0;
        #pragma unroll 1
        for (int q = 15; q >= 0; q--) {
            const int ncq = (2 * q + 9) >> 3;
            if (cid < accu + ncq) { qt = q; cch = cid - accu; break; }
            accu += ncq;
        }
    }
    const int njt = 2 * qt + 2;
    const int nc = (2 * qt + 9) >> 3;
    const int base = njt / nc, rem = njt % nc;
    const int jt0 = cch * base + (cch < rem ? cch : rem);
    const int jt1 = jt0 + base + (cch < rem ? 1 : 0);

    const float* Qb = Q + (size_t)b_ * SS * DD + h_ * HDIM;
    const float* Kb = K + (size_t)b_ * SS * DD + h_ * HDIM;
    const float* Vb = V + (size_t)b_ * SS * DD + h_ * HDIM;

    // Load Q transposed, pre-scaled into ex2 units
    #pragma unroll
    for (int l = 0; l < 8; l++) {
        const int idx = tid + l * 256;
        const int r = idx >> 4, d0 = (idx & 15) << 2;
        float4 v4 = *(const float4*)(Qb + (size_t)(qt * AQ + r) * DD + d0);
        sQt[d0 + 0][r] = v4.x * QSCL; sQt[d0 + 1][r] = v4.y * QSCL;
        sQt[d0 + 2][r] = v4.z * QSCL; sQt[d0 + 3][r] = v4.w * QSCL;
    }

    u64 lsum2[4];
    u64 o2[4][4];
    #pragma unroll
    for (int ip = 0; ip < 4; ip++) {
        lsum2[ip] = 0ull;
        #pragma unroll
        for (int j = 0; j < 4; j++) o2[ip][j] = 0ull;
    }

    for (int jt = jt0; jt < jt1; jt++) {
        __syncthreads();
        #pragma unroll
        for (int l = 0; l < 4; l++) {
            const int idx = tid + l * 256;
            const int r = idx >> 4, d0 = (idx & 15) << 2;
            float4 kv = *(const float4*)(Kb + (size_t)(jt * AK + r) * DD + d0);
            sKt[d0 + 0][r] = kv.x; sKt[d0 + 1][r] = kv.y;
            sKt[d0 + 2][r] = kv.z; sKt[d0 + 3][r] = kv.w;
            *(float4*)&sV[r][d0] =
                *(const float4*)(Vb + (size_t)(jt * AK + r) * DD + d0);
        }
        __syncthreads();

        const bool skip = (jt == 2 * qt + 1) && (ty < 8);
        if (!skip) {
            u64 sc2[4][4];
            #pragma unroll
            for (int ip = 0; ip < 4; ip++)
                #pragma unroll
                for (int j = 0; j < 4; j++) sc2[ip][j] = 0ull;

            #pragma unroll 8
            for (int dd = 0; dd < 64; dd++) {
                ulonglong2 qa = *(ulonglong2*)&sQt[dd][ty * 8];
                ulonglong2 qb = *(ulonglong2*)&sQt[dd][ty * 8 + 4];
                u64 ap[4] = { qa.x, qa.y, qb.x, qb.y };
                float4 kv = *(float4*)&sKt[dd][tx * 4];
                float kr[4] = { kv.x, kv.y, kv.z, kv.w };
                #pragma unroll
                for (int j = 0; j < 4; j++) {
                    u64 ks = pk2(kr[j], kr[j]);
                    #pragma unroll
                    for (int ip = 0; ip < 4; ip++) fma2(sc2[ip][j], ap[ip], ks);
                }
            }

            const bool msk = (jt == 2 * qt) ? (ty < 8) : (jt == 2 * qt + 1);
            #pragma unroll
            for (int ip = 0; ip < 4; ip++) {
                const int q0 = qt * AQ + ty * 8 + 2 * ip;
                #pragma unroll
                for (int j = 0; j < 4; j++) {
                    float2 c = up2(sc2[ip][j]);
                    float p0 = ex2(c.x);
                    float p1 = ex2(c.y);
                    if (msk) {
                        const int kg = jt * AK + tx * 4 + j;
                        if (kg > q0)     p0 = 0.0f;
                        if (kg > q0 + 1) p1 = 0.0f;
                    }
                    u64 pp = pk2(p0, p1);
                    add2(lsum2[ip], pp);
                    *(u64*)&sPt[tx * 4 + j][ty * 8 + 2 * ip] = pp;
                }
            }
        }
        __syncthreads();

        if (!skip) {
            #pragma unroll 8
            for (int kk = 0; kk < 64; kk++) {
                ulonglong2 pa = *(ulonglong2*)&sPt[kk][ty * 8];
                ulonglong2 pb = *(ulonglong2*)&sPt[kk][ty * 8 + 4];
                u64 ap[4] = { pa.x, pa.y, pb.x, pb.y };
                float4 vv = *(float4*)&sV[kk][tx * 4];
                float vr[4] = { vv.x, vv.y, vv.z, vv.w };
                #pragma unroll
                for (int j = 0; j < 4; j++) {
                    u64 vs = pk2(vr[j], vr[j]);
                    #pragma unroll
                    for (int ip = 0; ip < 4; ip++) fma2(o2[ip][j], ap[ip], vs);
                }
            }
        }
    }

    // ---- reduce row sums across tx lanes; write RAW partials ----
    float* pplane = part + (size_t)cch * NT * DD;
    float* lplane = lsg + (size_t)cch * NBH * SS + (size_t)bh * SS;
    #pragma unroll
    for (int ip = 0; ip < 4; ip++) {
        float2 c = up2(lsum2[ip]);
        float s0 = c.x, s1 = c.y;
        #pragma unroll
        for (int off = 8; off; off >>= 1) {
            s0 += __shfl_xor_sync(0xffffffffu, s0, off);
            s1 += __shfl_xor_sync(0xffffffffu, s1, off);
        }
        const int r0 = qt * AQ + ty * 8 + 2 * ip;
        if (tx == 0) {
            lplane[r0] = s0;
            lplane[r0 + 1] = s1;
        }
        float2 c0 = up2(o2[ip][0]), c1 = up2(o2[ip][1]);
        float2 c2 = up2(o2[ip][2]), c3 = up2(o2[ip][3]);
        float4 r0v = make_float4(c0.x, c1.x, c2.x, c3.x);
        float4 r1v = make_float4(c0.y, c1.y, c2.y, c3.y);
        *(float4*)(pplane + ((size_t)(b_ * SS + r0)) * DD + h_ * HDIM + tx * 4) = r0v;
        *(float4*)(pplane + ((size_t)(b_ * SS + r0 + 1)) * DD + h_ * HDIM + tx * 4) = r1v;
    }
}

// ---------------------------------------------------------------------------
// Combine split-k partials: out = (sum_c part_c) / (sum_c lsum_c)
// ---------------------------------------------------------------------------
__global__ __launch_bounds__(256)
void combine_k(const float* __restrict__ part, const float* __restrict__ lsg,
               float* __restrict__ out)
{
    const int idx = blockIdx.x * 256 + threadIdx.x;   // float4 id, NT*DD/4
    const int r  = idx / (DD / 4);          // token 0..4095
    const int c4 = idx % (DD / 4);
    const int d0 = c4 * 4;
    const int h  = d0 >> 6;
    const int b  = r >> 11;
    const int s  = r & (SS - 1);
    const int qt = s >> 7;
    const int nc = (2 * qt + 9) >> 3;       // 1..4 chunks for this row

    const size_t pidx = (size_t)r * DD + d0;
    const int    lidx = (b * HH + h) * SS + s;

    float4 acc = make_float4(0.f, 0.f, 0.f, 0.f);
    float ls = 0.f;
    for (int c = 0; c < nc; c++) {
        float4 p = *(const float4*)(part + (size_t)c * NT * DD + pidx);
        acc.x += p.x; acc.y += p.y; acc.z += p.z; acc.w += p.w;
        ls += lsg[(size_t)c * NBH * SS + lidx];
    }
    const float inv = 1.0f / ls;
    *(float4*)(out + pidx) =
        make_float4(acc.x * inv, acc.y * inv, acc.z * inv, acc.w * inv);
}

// ---------------------------------------------------------------------------
// Launch
// ---------------------------------------------------------------------------
extern "C" void kernel_launch(void* const* d_in, const int* in_sizes, int n_in,
                              void* d_out, int out_size)
{
    (void)n_in; (void)in_sizes; (void)out_size;

    const float* x  = (const float*)d_in[0];
    const float* wq = (const float*)d_in[2];
    const float* bq = (const float*)d_in[3];
    const float* wk = (const float*)d_in[4];
    const float* bk = (const float*)d_in[5];
    const float* wv = (const float*)d_in[6];
    const float* bv = (const float*)d_in[7];
    const float* wo = (const float*)d_in[8];
    const float* bo = (const float*)d_in[9];
    float* out = (float*)d_out;

    static float *q = nullptr, *k, *v, *att, *part, *ls;
    if (!q) {
        cudaGetSymbolAddress((void**)&q,    g_q);
        cudaGetSymbolAddress((void**)&k,    g_k);
        cudaGetSymbolAddress((void**)&v,    g_v);
        cudaGetSymbolAddress((void**)&att,  g_att);
        cudaGetSymbolAddress((void**)&part, g_part);
        cudaGetSymbolAddress((void**)&ls,   g_ls);
        cudaFuncSetAttribute(attn_f2,
            cudaFuncAttributeMaxDynamicSharedMemorySize, ATTN_SMEM);
    }

    // Fused QKV projection: BN=128, 32 x 18 = 576 CTAs (1.95 waves)
    dim3 gq(NT / TM, 3 * (DD / 128));
    gemm3t<128><<<gq, 256>>>(x, wq, wk, wv, bq, bk, bv, q, k, v);

    // Attention split-k: 40 uniform chunks x 24 bh = 960 CTAs
    dim3 ag(NCHUNK, NBH);
    attn_f2<<<ag, 256, ATTN_SMEM>>>(q, k, v, part, ls);

    // Combine partials -> g_att
    combine_k<<<NT * DD / 4 / 256, 256>>>(part, ls, att);

    // Output projection: BN=64, 32 x 12 = 384 CTAs (1.3 waves)
    dim3 go(NT / TM, DD / 64);
    gemm3t<64><<<go, 256>>>(att, wo, wo, wo, bo, bo, bo, out, out, out);
}